// round 10
// baseline (speedup 1.0000x reference)
#include <cuda_runtime.h>

// Gray-Scott residual with t-loop register reuse: each thread owns a (b, 2-row, 4-col)
// tile and marches t=0..19, keeping 3-deep center history in registers so time
// derivatives need ZERO extra loads. Spatial: aligned LDG.128 (center rows) +
// aligned LDG.64 pairs (vertical halo rows). No shuffles, no smem.
// input (20,8,3,256,256) f32 -> f_u, f_v each (20,8,1,252,252) concatenated.

#define T_DIM 20
#define B_DIM 8
#define WW 256
#define OH 252
#define OW 252
#define CS 65536                   // 256*256
#define OPLANE (OH * OW)           // 63504
#define NOUT (T_DIM * B_DIM * OPLANE)

#define C1f (4.0f / 3.0f)
#define C2f (-1.0f / 12.0f)
#define INV_DX2 40.96f

// Narrow row: exactly cols col0+2..col0+5 via two aligned LDG.64.
__device__ __forceinline__ void ldn(const float* __restrict__ p, float n[4])
{
    const float2 a = *reinterpret_cast<const float2*>(p + 2);
    const float2 b = *reinterpret_cast<const float2*>(p + 4);
    n[0] = a.x; n[1] = a.y; n[2] = b.x; n[3] = b.y;
}

// One channel, one t: scaled laplacian lap[8] and centers c[8] (2 rows x 4 cols).
// p points at (row yy0, col col0) of the channel plane.
__device__ __forceinline__ void spatial(const float* __restrict__ p,
                                        float lap[8], float c[8])
{
    const float4 c2a = *reinterpret_cast<const float4*>(p + 2 * WW);
    const float4 c2b = *reinterpret_cast<const float4*>(p + 2 * WW + 4);
    const float4 c3a = *reinterpret_cast<const float4*>(p + 3 * WW);
    const float4 c3b = *reinterpret_cast<const float4*>(p + 3 * WW + 4);
    float n0[4], n1[4], n4[4], n5[4];
    ldn(p,          n0);
    ldn(p + 1 * WW, n1);
    ldn(p + 4 * WW, n4);
    ldn(p + 5 * WW, n5);

    const float c2[8] = { c2a.x, c2a.y, c2a.z, c2a.w, c2b.x, c2b.y, c2b.z, c2b.w };
    const float c3[8] = { c3a.x, c3a.y, c3a.z, c3a.w, c3b.x, c3b.y, c3b.z, c3b.w };

    #pragma unroll
    for (int k = 0; k < 4; k++) {
        const float cc0 = c2[k + 2];
        const float cc1 = c3[k + 2];
        lap[k]     = (C1f * (c2[k + 1] + c2[k + 3] + n1[k] + cc1)
                    + C2f * (c2[k] + c2[k + 4] + n0[k] + n4[k])
                    - 5.0f * cc0) * INV_DX2;
        lap[k + 4] = (C1f * (c3[k + 1] + c3[k + 3] + cc0 + n4[k])
                    + C2f * (c3[k] + c3[k + 4] + n1[k] + n5[k])
                    - 5.0f * cc1) * INV_DX2;
        c[k]     = cc0;
        c[k + 4] = cc1;
    }
}

__device__ __forceinline__ void emit(float* __restrict__ out, int tb, int yy0, int col0,
                                     const float ru[8], const float rv[8])
{
    const size_t o = (size_t)tb * OPLANE + (size_t)yy0 * OW + col0;
    *reinterpret_cast<float4*>(out + o)             = make_float4(ru[0], ru[1], ru[2], ru[3]);
    *reinterpret_cast<float4*>(out + o + OW)        = make_float4(ru[4], ru[5], ru[6], ru[7]);
    *reinterpret_cast<float4*>(out + o + NOUT)      = make_float4(rv[0], rv[1], rv[2], rv[3]);
    *reinterpret_cast<float4*>(out + o + NOUT + OW) = make_float4(rv[4], rv[5], rv[6], rv[7]);
}

__global__ __launch_bounds__(64) void grayscott_loss_kernel(
    const float* __restrict__ in, float* __restrict__ out)
{
    const int tx   = threadIdx.x;               // 0..63
    const int col0 = min(4 * tx, 248);          // tx==63 duplicates tx==62 (benign)
    const int yy0  = blockIdx.x * 2;            // output rows yy0, yy0+1 (0..250)
    const int b    = blockIdx.y;                // 0..7

    const float Du = 0.16f, Dv = 0.08f, Ff = 0.06f, FpK = 0.122f;

    float ucm2[8], ucm1[8], vcm2[8], vcm1[8];   // center history: t-2, t-1
    float ppu[8], ppv[8];                       // partial residual at t-1
    float q0u[8], q0v[8];                       // t=0 one-sided accumulator

    #pragma unroll 4
    for (int t = 0; t < T_DIM; t++) {
        const float* pu = in + ((size_t)(t * B_DIM + b) * 3 + 1) * CS
                             + (size_t)yy0 * WW + col0;
        const float* pv = pu + CS;

        float lapu[8], ucn[8], lapv[8], vcn[8];
        spatial(pu, lapu, ucn);
        spatial(pv, lapv, vcn);

        // partial residual (everything except the time derivative)
        float pnu[8], pnv[8];
        #pragma unroll
        for (int k = 0; k < 8; k++) {
            const float uvv = ucn[k] * vcn[k] * vcn[k];
            pnu[k] = Du * lapu[k] - uvv + Ff * (1.0f - ucn[k]);
            pnv[k] = Dv * lapv[k] + uvv - FpK * vcn[k];
        }

        if (t >= 2) {                       // central: res(t-1) = p(t-1) - 10*(c(t)-c(t-2))
            float ru[8], rv[8];
            #pragma unroll
            for (int k = 0; k < 8; k++) {
                ru[k] = ppu[k] - 10.0f * (ucn[k] - ucm2[k]);
                rv[k] = ppv[k] - 10.0f * (vcn[k] - vcm2[k]);
            }
            emit(out, (t - 1) * B_DIM + b, yy0, col0, ru, rv);
        }
        if (t == 1) {                       // res(0) = p0 + 30*c0 - 40*c1 + 10*c2 (c2 pending)
            #pragma unroll
            for (int k = 0; k < 8; k++) {
                q0u[k] = ppu[k] + 30.0f * ucm1[k] - 40.0f * ucn[k];
                q0v[k] = ppv[k] + 30.0f * vcm1[k] - 40.0f * vcn[k];
            }
        }
        if (t == 2) {
            float ru[8], rv[8];
            #pragma unroll
            for (int k = 0; k < 8; k++) {
                ru[k] = q0u[k] + 10.0f * ucn[k];
                rv[k] = q0v[k] + 10.0f * vcn[k];
            }
            emit(out, 0 * B_DIM + b, yy0, col0, ru, rv);
        }
        if (t == T_DIM - 1) {               // res(19) = p19 - (30*c19 - 40*c18 + 10*c17)
            float ru[8], rv[8];
            #pragma unroll
            for (int k = 0; k < 8; k++) {
                ru[k] = pnu[k] - (30.0f * ucn[k] - 40.0f * ucm1[k] + 10.0f * ucm2[k]);
                rv[k] = pnv[k] - (30.0f * vcn[k] - 40.0f * vcm1[k] + 10.0f * vcm2[k]);
            }
            emit(out, (T_DIM - 1) * B_DIM + b, yy0, col0, ru, rv);
        }

        // shift history
        #pragma unroll
        for (int k = 0; k < 8; k++) {
            ucm2[k] = ucm1[k];  ucm1[k] = ucn[k];
            vcm2[k] = vcm1[k];  vcm1[k] = vcn[k];
            ppu[k]  = pnu[k];   ppv[k]  = pnv[k];
        }
    }
}

extern "C" void kernel_launch(void* const* d_in, const int* in_sizes, int n_in,
                              void* d_out, int out_size)
{
    const float* in = (const float*)d_in[0];
    float* out = (float*)d_out;
    dim3 block(64, 1, 1);                  // 2 warps
    dim3 grid(126, B_DIM, 1);              // 126 y-tiles x 8 batches = 1008 CTAs
    grayscott_loss_kernel<<<grid, block>>>(in, out);
}

// round 11
// speedup vs baseline: 1.4137x; 1.4137x over previous
#include <cuda_runtime.h>

// Gray-Scott residual, Tc=2 time-chunking: each thread computes a 2(y) x 4(x) tile
// for two consecutive t values. Spatial stencils loaded for t=a,a+1; time derivative
// uses center-only loads of t=a-1 and t=a+2 (4 cols, LDG.64 pairs). No shuffles/smem.
// input (20,8,3,256,256) f32 -> f_u, f_v each (20,8,1,252,252) concatenated.

#define T_DIM 20
#define B_DIM 8
#define WW 256
#define OH 252
#define OW 252
#define CS 65536
#define OPLANE (OH * OW)           // 63504
#define NOUT (T_DIM * B_DIM * OPLANE)

#define C1f (4.0f / 3.0f)
#define C2f (-1.0f / 12.0f)
#define INV_DX2 40.96f

// Exactly cols +2..+5 of one row via two aligned LDG.64.
__device__ __forceinline__ void ldn(const float* __restrict__ p, float n[4])
{
    const float2 a = *reinterpret_cast<const float2*>(p + 2);
    const float2 b = *reinterpret_cast<const float2*>(p + 4);
    n[0] = a.x; n[1] = a.y; n[2] = b.x; n[3] = b.y;
}

// Full spatial stencil for one channel at one t: scaled lap[8] + centers c[8].
__device__ __forceinline__ void spatial(const float* __restrict__ p,
                                        float lap[8], float c[8])
{
    const float4 c2a = *reinterpret_cast<const float4*>(p + 2 * WW);
    const float4 c2b = *reinterpret_cast<const float4*>(p + 2 * WW + 4);
    const float4 c3a = *reinterpret_cast<const float4*>(p + 3 * WW);
    const float4 c3b = *reinterpret_cast<const float4*>(p + 3 * WW + 4);
    float n0[4], n1[4], n4[4], n5[4];
    ldn(p,          n0);
    ldn(p + 1 * WW, n1);
    ldn(p + 4 * WW, n4);
    ldn(p + 5 * WW, n5);

    const float c2[8] = { c2a.x, c2a.y, c2a.z, c2a.w, c2b.x, c2b.y, c2b.z, c2b.w };
    const float c3[8] = { c3a.x, c3a.y, c3a.z, c3a.w, c3b.x, c3b.y, c3b.z, c3b.w };

    #pragma unroll
    for (int k = 0; k < 4; k++) {
        const float cc0 = c2[k + 2];
        const float cc1 = c3[k + 2];
        lap[k]     = (C1f * (c2[k + 1] + c2[k + 3] + n1[k] + cc1)
                    + C2f * (c2[k] + c2[k + 4] + n0[k] + n4[k])
                    - 5.0f * cc0) * INV_DX2;
        lap[k + 4] = (C1f * (c3[k + 1] + c3[k + 3] + cc0 + n4[k])
                    + C2f * (c3[k] + c3[k + 4] + n1[k] + n5[k])
                    - 5.0f * cc1) * INV_DX2;
        c[k]     = cc0;
        c[k + 4] = cc1;
    }
}

// Center-only tile (rows +2,+3, cols +2..+5).
__device__ __forceinline__ void centers(const float* __restrict__ p, float c[8])
{
    ldn(p + 2 * WW, c);
    ldn(p + 3 * WW, c + 4);
}

__device__ __forceinline__ void emit(float* __restrict__ out, int tb, int yy0, int col0,
                                     const float ru[8], const float rv[8])
{
    const size_t o = (size_t)tb * OPLANE + (size_t)yy0 * OW + col0;
    *reinterpret_cast<float4*>(out + o)             = make_float4(ru[0], ru[1], ru[2], ru[3]);
    *reinterpret_cast<float4*>(out + o + OW)        = make_float4(ru[4], ru[5], ru[6], ru[7]);
    *reinterpret_cast<float4*>(out + o + NOUT)      = make_float4(rv[0], rv[1], rv[2], rv[3]);
    *reinterpret_cast<float4*>(out + o + NOUT + OW) = make_float4(rv[4], rv[5], rv[6], rv[7]);
}

__global__ __launch_bounds__(128) void grayscott_loss_kernel(
    const float* __restrict__ in, float* __restrict__ out)
{
    const int tx    = threadIdx.x;                 // 0..63
    const int ty    = threadIdx.y;                 // 0..1
    const int col0  = min(4 * tx, 248);            // tx==63 duplicates tx==62 (benign)
    const int yy0   = blockIdx.x * 4 + ty * 2;     // output rows yy0, yy0+1
    const int bc    = blockIdx.y;                  // 0..79
    const int b     = bc & 7;
    const int a     = (bc >> 3) * 2;               // first t of the chunk: 0,2,..,18

    const float Du = 0.16f, Dv = 0.08f, Ff = 0.06f, FpK = 0.122f;

    const size_t sp_off = (size_t)yy0 * WW + col0;
    const float* pa = in + ((size_t)(a * B_DIM + b) * 3 + 1) * CS + sp_off;        // u, t=a
    const float* pb = in + ((size_t)((a + 1) * B_DIM + b) * 3 + 1) * CS + sp_off;  // u, t=a+1

    // ---- t = a ----
    float uca[8], gua[8];
    {
        float lap[8];
        spatial(pa, lap, uca);
        #pragma unroll
        for (int k = 0; k < 8; k++) gua[k] = Du * lap[k] + Ff * (1.0f - uca[k]);
    }
    float vca[8], pua[8], pva[8];
    {
        float lap[8];
        spatial(pa + CS, lap, vca);
        #pragma unroll
        for (int k = 0; k < 8; k++) {
            const float uvv = uca[k] * vca[k] * vca[k];
            pua[k] = gua[k] - uvv;
            pva[k] = Dv * lap[k] + uvv - FpK * vca[k];
        }
    }

    // ---- t = a+1 ----
    float ucb[8], gub[8];
    {
        float lap[8];
        spatial(pb, lap, ucb);
        #pragma unroll
        for (int k = 0; k < 8; k++) gub[k] = Du * lap[k] + Ff * (1.0f - ucb[k]);
    }
    float vcb[8], pub[8], pvb[8];
    {
        float lap[8];
        spatial(pb + CS, lap, vcb);
        #pragma unroll
        for (int k = 0; k < 8; k++) {
            const float uvv = ucb[k] * vcb[k] * vcb[k];
            pub[k] = gub[k] - uvv;
            pvb[k] = Dv * lap[k] + uvv - FpK * vcb[k];
        }
    }

    // ---- boundary centers: t = a-1 and t = a+2 ----
    float ucm[8], vcm[8], ucp[8], vcp[8];
    if (a > 0) {
        const float* pm = in + ((size_t)((a - 1) * B_DIM + b) * 3 + 1) * CS + sp_off;
        centers(pm, ucm);
        centers(pm + CS, vcm);
    }
    if (a + 2 < T_DIM) {
        const float* pp = in + ((size_t)((a + 2) * B_DIM + b) * 3 + 1) * CS + sp_off;
        centers(pp, ucp);
        centers(pp + CS, vcp);
    }

    // ---- residual at t = a ----
    {
        float ru[8], rv[8];
        if (a == 0) {
            // one-sided: td0 = (-1.5 c0 + 2 c1 - 0.5 c2)/dt -> res0 = p0 + 30c0 - 40c1 + 10c2
            #pragma unroll
            for (int k = 0; k < 8; k++) {
                ru[k] = pua[k] + 30.0f * uca[k] - 40.0f * ucb[k] + 10.0f * ucp[k];
                rv[k] = pva[k] + 30.0f * vca[k] - 40.0f * vcb[k] + 10.0f * vcp[k];
            }
        } else {
            #pragma unroll
            for (int k = 0; k < 8; k++) {
                ru[k] = pua[k] - 10.0f * (ucb[k] - ucm[k]);
                rv[k] = pva[k] - 10.0f * (vcb[k] - vcm[k]);
            }
        }
        emit(out, a * B_DIM + b, yy0, col0, ru, rv);
    }

    // ---- residual at t = a+1 ----
    {
        float ru[8], rv[8];
        if (a + 1 == T_DIM - 1) {
            // one-sided: res19 = p19 - 30c19 + 40c18 - 10c17
            #pragma unroll
            for (int k = 0; k < 8; k++) {
                ru[k] = pub[k] - 30.0f * ucb[k] + 40.0f * uca[k] - 10.0f * ucm[k];
                rv[k] = pvb[k] - 30.0f * vcb[k] + 40.0f * vca[k] - 10.0f * vcm[k];
            }
        } else {
            #pragma unroll
            for (int k = 0; k < 8; k++) {
                ru[k] = pub[k] - 10.0f * (ucp[k] - uca[k]);
                rv[k] = pvb[k] - 10.0f * (vcp[k] - vca[k]);
            }
        }
        emit(out, (a + 1) * B_DIM + b, yy0, col0, ru, rv);
    }
}

extern "C" void kernel_launch(void* const* d_in, const int* in_sizes, int n_in,
                              void* d_out, int out_size)
{
    const float* in = (const float*)d_in[0];
    float* out = (float*)d_out;
    dim3 block(64, 2, 1);                        // 128 threads
    dim3 grid(OH / 4, B_DIM * (T_DIM / 2), 1);   // 63 x 80 = 5040 CTAs
    grayscott_loss_kernel<<<grid, block>>>(in, out);
}